// round 13
// baseline (speedup 1.0000x reference)
#include <cuda_runtime.h>
#include <cuda_fp16.h>
#include <math.h>
#include <stdint.h>

// Problem constants
#define NB 4
#define LQ 8192
#define SSEQ 8192
#define CC 256
#define HH 8
#define DD 32
#define MTOT (NB*LQ)     // 32768 query rows
#define MSRC (NB*SSEQ)   // 32768 source rows
#define SUBC 256         // 32-row chunks per batch
#define KVSZ (HH*DD*DD)  // 8192 per batch

// fp16 weight arena segment offsets (halves)
#define WH_Q  0
#define WH_K  65536      // Wk rows 0..255 then Wv rows 256..511 (contiguous => merged)
#define WH_M  196608
#define WH_1  262144
#define WH_2  524288
#define WH_TOT 655360

// Scratch (device globals: no allocation allowed)
__device__ float g_query[MTOT*CC];
__device__ float g_kv[(size_t)MSRC*2*CC];     // merged key|value, row stride 512
__device__ float g_Kpart[(size_t)NB*SUBC*CC];
__device__ float g_KVpart[(size_t)NB*SUBC*KVSZ];
__device__ float g_Ksum[NB*CC];
__device__ float g_KV[NB*KVSZ];
__device__ float g_msg[MTOT*CC];
__device__ float g_h2[MTOT*CC];
// fp16 activation tensors (single-term)
__device__ __half g_xh[MTOT*CC];
__device__ __half g_sh[MSRC*CC];
__device__ __half g_qh[MTOT*CC];       // queried
__device__ __half g_m1h[MTOT*CC];
__device__ __half g_hbh[(size_t)MTOT*2*CC];
__device__ __half g_wh[WH_TOT];

// ===========================================================================
// Helpers
// ===========================================================================
__device__ __forceinline__ uint32_t smem_u32(const void* p) {
    uint32_t a;
    asm("{ .reg .u64 t; cvta.to.shared.u64 t, %1; cvt.u32.u64 %0, t; }"
        : "=r"(a) : "l"(p));
    return a;
}

#define CP_ASYNC16(dst_u32, src_ptr) \
    asm volatile("cp.async.cg.shared.global [%0], [%1], 16;" \
        :: "r"(dst_u32), "l"(src_ptr))
#define CP_COMMIT() asm volatile("cp.async.commit_group;")
#define CP_WAIT1()  asm volatile("cp.async.wait_group 1;")

#define LDSM_X4(r0,r1,r2,r3, addr) \
    asm volatile("ldmatrix.sync.aligned.m8n8.x4.shared.b16 {%0,%1,%2,%3}, [%4];" \
        : "=r"(r0), "=r"(r1), "=r"(r2), "=r"(r3) : "r"(addr))

__device__ __forceinline__ void mma16816(float* c, const uint32_t* a, const uint32_t* b) {
    asm volatile(
        "mma.sync.aligned.m16n8k16.row.col.f32.f16.f16.f32 "
        "{%0,%1,%2,%3}, {%4,%5,%6,%7}, {%8,%9}, {%0,%1,%2,%3};"
        : "+f"(c[0]), "+f"(c[1]), "+f"(c[2]), "+f"(c[3])
        : "r"(a[0]), "r"(a[1]), "r"(a[2]), "r"(a[3]), "r"(b[0]), "r"(b[1]));
}

// ===========================================================================
// One-time converts (round-to-nearest fp16)
// ===========================================================================
__global__ void convert_act(const float* __restrict__ in,
                            __half* __restrict__ hi, int n4)
{
    int i = blockIdx.x * 256 + threadIdx.x;
    if (i >= n4) return;
    float4 v = ((const float4*)in)[i];
    __half h[4] = {__float2half_rn(v.x), __float2half_rn(v.y),
                   __float2half_rn(v.z), __float2half_rn(v.w)};
    ((uint2*)hi)[i] = *(uint2*)h;
}

__global__ void convert_w(const float* __restrict__ Wq, const float* __restrict__ Wk,
                          const float* __restrict__ Wv, const float* __restrict__ Wm,
                          const float* __restrict__ W1, const float* __restrict__ W2,
                          __half* __restrict__ arena)
{
    int idx = (blockIdx.x * 256 + threadIdx.x) * 4;
    if (idx >= WH_TOT) return;
    const float* src; int off;
    if (idx < WH_1) {
        int seg = idx >> 16;
        src = (seg == 0) ? Wq : (seg == 1) ? Wk : (seg == 2) ? Wv : Wm;
        off = idx & 65535;
    } else if (idx < WH_2) { src = W1; off = idx - WH_1; }
    else                   { src = W2; off = idx - WH_2; }
    float4 v = *(const float4*)(src + off);
    __half h[4] = {__float2half_rn(v.x), __float2half_rn(v.y),
                   __float2half_rn(v.z), __float2half_rn(v.w)};
    *(uint2*)(arena + idx) = *(uint2*)h;
}

// ===========================================================================
// Tensor-core GEMM, cp.async 3-stage pipeline, single-term fp16:
//   Y[m,n] = act( sum_k Ah[m,k] * Bh[n,k] )
// Tile 128x128xBK64, 256 threads / 8 warps, warp tile 64x32, 2 CTAs/SM.
// BK=64 halves the per-chunk barrier/wait overhead count vs BK=32.
// Template NK = K/64 (fully unrolls), SPLIT = concat-A (W1 GEMM).
// ===========================================================================
#define BM 128
#define BN 128
#define BK 64
#define STAGES 3
#define SSTR 72                 // padded fp16 row stride (144B): conflict-free ldmatrix
#define SA (128*SSTR*2)         // 18432 B (A tile)
#define SB (128*SSTR*2)         // 18432 B (B tile)
#define STG (SA + SB)           // 36864
#define SMEM_DYN (STAGES*STG)   // 110592 (2 CTAs/SM: 221KB <= 227KB)

template<int NK, bool SPLIT>
__global__ void __launch_bounds__(256, 2) hgemm(
    const __half* __restrict__ Ah, const __half* __restrict__ A2h,
    int Ksplit, int lda, const __half* __restrict__ W,
    float* __restrict__ Y, __half* __restrict__ Yh,
    int Nn, int relu)
{
    constexpr int K = NK * BK;
    extern __shared__ __align__(16) char smem[];
    const uint32_t sb = smem_u32(smem);

    const int tid = threadIdx.x;
    const int lane = tid & 31;
    const int wid = tid >> 5;
    const int bm = blockIdx.y * BM;
    const int bn = blockIdx.x * BN;
    const int wm = (wid >> 2) * 64;   // 0/64
    const int wn = (wid & 3) * 32;    // 0..96

    // loader mapping: 4 threads per row; each thread covers half-chunks at
    // ac0 and ac0+32 (halves); rows arow and arow+64.
    const int arow = tid >> 2;          // 0..63
    const int ac0 = (tid & 3) * 8;      // 0,8,16,24
    const uint32_t sO00 = (uint32_t)(arow * SSTR + ac0) * 2;
    const uint32_t sO01 = (uint32_t)(arow * SSTR + ac0 + 32) * 2;
    const uint32_t sO10 = sO00 + (uint32_t)(64 * SSTR * 2);
    const uint32_t sO11 = sO01 + (uint32_t)(64 * SSTR * 2);

    // issue loads for chunk ck into stage st
    auto load_chunk = [&](int ck, int st) {
        const int k0 = ck * BK;
        const __half* ah = Ah;
        int kk0 = k0;
        if (SPLIT && k0 >= Ksplit) { ah = A2h; kk0 = k0 - Ksplit; }
        const uint32_t base = sb + st * STG;
        const __half* a0 = ah + (size_t)(bm + arow) * lda + kk0;
        const __half* a1 = ah + (size_t)(bm + 64 + arow) * lda + kk0;
        const __half* b0 = W + (size_t)(bn + arow) * K + k0;
        const __half* b1 = W + (size_t)(bn + 64 + arow) * K + k0;
        CP_ASYNC16(base + sO00, a0 + ac0);
        CP_ASYNC16(base + sO01, a0 + ac0 + 32);
        CP_ASYNC16(base + sO10, a1 + ac0);
        CP_ASYNC16(base + sO11, a1 + ac0 + 32);
        CP_ASYNC16(base + SA + sO00, b0 + ac0);
        CP_ASYNC16(base + SA + sO01, b0 + ac0 + 32);
        CP_ASYNC16(base + SA + sO10, b1 + ac0);
        CP_ASYNC16(base + SA + sO11, b1 + ac0 + 32);
    };

    float c[4][4][4];
#pragma unroll
    for (int mi = 0; mi < 4; mi++)
#pragma unroll
        for (int ni = 0; ni < 4; ni++)
#pragma unroll
            for (int i = 0; i < 4; i++) c[mi][ni][i] = 0.f;

    load_chunk(0, 0); CP_COMMIT();
    load_chunk(1, 1); CP_COMMIT();

#pragma unroll
    for (int ck = 0; ck < NK; ck++) {
        CP_WAIT1();
        __syncthreads();   // orders mma(ck-1) of all warps before that slot is refilled

        const int nc = ck + STAGES - 1;
        if (nc < NK) load_chunk(nc, nc % STAGES);
        CP_COMMIT();

        const uint32_t sAh = sb + (ck % STAGES) * STG;
        const uint32_t sBh = sAh + SA;
#pragma unroll
        for (int kk = 0; kk < 4; kk++) {
            uint32_t ahf[4][4], bhf[4][2];
            // A frags: 4 x ldmatrix.x4 (rows wm+mi*16+(lane&15), k kk*16+(lane>>4)*8)
            const uint32_t aoff =
                ((wm + (lane & 15)) * SSTR + kk * 16 + (lane >> 4) * 8) * 2;
#pragma unroll
            for (int mi = 0; mi < 4; mi++)
                LDSM_X4(ahf[mi][0], ahf[mi][1], ahf[mi][2], ahf[mi][3],
                        sAh + aoff + mi * 16 * SSTR * 2);
            // B frags: 2 x ldmatrix.x4, each covers ni pair (2p, 2p+1)
            const uint32_t boff =
                ((wn + (lane >> 4) * 8 + (lane & 7)) * SSTR
                 + kk * 16 + ((lane >> 3) & 1) * 8) * 2;
#pragma unroll
            for (int p = 0; p < 2; p++)
                LDSM_X4(bhf[2*p][0], bhf[2*p][1], bhf[2*p+1][0], bhf[2*p+1][1],
                        sBh + boff + p * 16 * SSTR * 2);
#pragma unroll
            for (int mi = 0; mi < 4; mi++)
#pragma unroll
                for (int ni = 0; ni < 4; ni++)
                    mma16816(c[mi][ni], ahf[mi], bhf[ni]);
        }
    }

    // Epilogue: c frag mapping (m16n8): rows lane/4 (+8), cols (lane%4)*2 (+1)
    const int grp = lane >> 2;
    const int tg = (lane & 3) * 2;
#pragma unroll
    for (int mi = 0; mi < 4; mi++)
#pragma unroll
        for (int ni = 0; ni < 4; ni++) {
            float v[4] = {c[mi][ni][0], c[mi][ni][1], c[mi][ni][2], c[mi][ni][3]};
            if (relu) {
#pragma unroll
                for (int i = 0; i < 4; i++) v[i] = fmaxf(v[i], 0.f);
            }
            const size_t r0 = (size_t)(bm + wm + mi * 16 + grp) * Nn + bn + wn + ni * 8 + tg;
            const size_t r1 = r0 + (size_t)8 * Nn;
            if (Y) {
                *(float2*)(Y + r0) = make_float2(v[0], v[1]);
                *(float2*)(Y + r1) = make_float2(v[2], v[3]);
            }
            if (Yh) {
                __half h[4] = {__float2half_rn(v[0]), __float2half_rn(v[1]),
                               __float2half_rn(v[2]), __float2half_rn(v[3])};
                *(uint32_t*)(Yh + r0) = *(uint32_t*)&h[0];
                *(uint32_t*)(Yh + r1) = *(uint32_t*)&h[2];
            }
        }
}

// ---------------------------------------------------------------------------
// Stage B (warp-per-head, 32-row chunks, grid 1024); reads merged kv buffer
// (row stride 512: key at col c, value at col 256+c).
// ---------------------------------------------------------------------------
__global__ void __launch_bounds__(256) stageB_kernel(
    const float* __restrict__ kvbuf,
    const float* __restrict__ spe, const float* __restrict__ smask,
    float* __restrict__ Kpart, float* __restrict__ KVpart)
{
    const int n = blockIdx.x / SUBC;
    const int chunk = blockIdx.x % SUBC;
    const int s0 = chunk * 32;
    const int h = threadIdx.x >> 5;
    const int lane = threadIdx.x & 31;
    const int c = h * 32 + lane;

    float acc[32];
#pragma unroll
    for (int d = 0; d < 32; d++) acc[d] = 0.f;
    float accKs = 0.f;

    const size_t pebase = ((size_t)n * SSEQ + s0) * CC;
    const size_t kvbase = ((size_t)n * SSEQ + s0) * (2*CC);
    const float* mrow = smask + (size_t)n * SSEQ + s0;
    for (int r = 0; r < 32; r++) {
        const size_t kvrow = kvbase + (size_t)r * (2*CC);
        float kc = kvbuf[kvrow + c];
        float vc = kvbuf[kvrow + CC + c];
        float2 pe = *(const float2*)(spe + (pebase + (size_t)r * CC + c) * 2);
        float m  = mrow[r];
        float kp = __shfl_xor_sync(0xffffffffu, kc, 1);
        float vp = __shfl_xor_sync(0xffffffffu, vc, 1);
        float k2 = (lane & 1) ? kp : -kp;
        float v2 = (lane & 1) ? vp : -vp;
        float Kf   = (kc > 0.f ? kc + 1.f : expf(kc)) * m;
        float Kpos = (kc * pe.x + k2 * pe.y) * m;
        float Vr   = (vc * pe.x + v2 * pe.y) * m;
        accKs += Kf;
#pragma unroll
        for (int d = 0; d < 32; d++) {
            float a = __shfl_sync(0xffffffffu, Kpos, d);
            acc[d] = fmaf(a, Vr, acc[d]);
        }
    }
    Kpart[(size_t)(n*SUBC + chunk)*CC + c] = accKs;
    const size_t kvb = (size_t)(n*SUBC + chunk)*KVSZ + h*1024;
#pragma unroll
    for (int d = 0; d < 32; d++)
        KVpart[kvb + d*32 + lane] = acc[d];
}

// Fixed-order reduction of chunk partials -> Ksum, KV (deterministic)
__global__ void __launch_bounds__(256) reduce_parts(
    const float* __restrict__ Kpart, const float* __restrict__ KVpart,
    float* __restrict__ Ksum, float* __restrict__ KV)
{
    int idx = blockIdx.x * 256 + threadIdx.x;
    if (idx < NB*CC) {
        int n = idx / CC, c = idx % CC;
        float s = 0.f;
        for (int ch = 0; ch < SUBC; ch++)
            s += Kpart[(size_t)(n*SUBC + ch)*CC + c];
        Ksum[idx] = s;
        return;
    }
    int kidx = idx - NB*CC;
    if (kidx < NB*KVSZ) {
        int n = kidx / KVSZ, e = kidx % KVSZ;
        float s = 0.f;
        for (int ch = 0; ch < SUBC; ch++)
            s += KVpart[(size_t)(n*SUBC + ch)*KVSZ + e];
        KV[kidx] = s;
    }
}

// ---------------------------------------------------------------------------
// Stage C (warp-per-head): writes queried directly as fp16
// ---------------------------------------------------------------------------
__global__ void __launch_bounds__(256) stageC_kernel(
    const float* __restrict__ query, const float* __restrict__ xpe,
    const float* __restrict__ xmask, const float* __restrict__ Ksum,
    const float* __restrict__ KV, __half* __restrict__ qh)
{
    const int n = blockIdx.x / SUBC;
    const int l0 = (blockIdx.x % SUBC) * 32;
    const int h = threadIdx.x >> 5;
    const int lane = threadIdx.x & 31;
    const int c = h * 32 + lane;

    float kvreg[32];
#pragma unroll
    for (int d = 0; d < 32; d++)
        kvreg[d] = KV[(size_t)n*KVSZ + h*1024 + d*32 + lane];
    const float ks = Ksum[n*CC + c];

    const size_t base = ((size_t)n * LQ + l0) * CC;
    const float* mrow = xmask + (size_t)n * LQ + l0;
    for (int r = 0; r < 32; r++) {
        const size_t row = base + (size_t)r * CC;
        float q  = query[row + c];
        float2 pe = *(const float2*)(xpe + (row + c) * 2);
        float m  = mrow[r];
        float qp = __shfl_xor_sync(0xffffffffu, q, 1);
        float q2 = (lane & 1) ? qp : -qp;
        float Qf   = (q > 0.f ? q + 1.f : expf(q)) * m;
        float Qpos = (q * pe.x + q2 * pe.y) * m;

        float p = Qf * ks;
#pragma unroll
        for (int o = 16; o; o >>= 1) p += __shfl_xor_sync(0xffffffffu, p, o);
        float z = 1.f / (p + 1e-6f);

        float out = 0.f;
#pragma unroll
        for (int d = 0; d < 32; d++) {
            float a = __shfl_sync(0xffffffffu, Qpos, d);
            out = fmaf(a, kvreg[d], out);
        }
        qh[row + c] = __float2half_rn(out * z);
    }
}

// ---------------------------------------------------------------------------
// LayerNorm over last dim (256); one warp per row.
// Writes fp32 (with optional residual) and/or fp16.
// ---------------------------------------------------------------------------
__global__ void __launch_bounds__(256) ln_kernel(
    const float* __restrict__ in, const float* __restrict__ g,
    const float* __restrict__ b, const float* __restrict__ resid,
    float* __restrict__ out, __half* __restrict__ outh)
{
    const int row = blockIdx.x * 8 + (threadIdx.x >> 5);
    const int lane = threadIdx.x & 31;
    const float* p = in + (size_t)row * CC;
    float v[8];
    float s = 0.f;
#pragma unroll
    for (int i = 0; i < 8; i++) { v[i] = p[lane + i*32]; s += v[i]; }
#pragma unroll
    for (int o = 16; o; o >>= 1) s += __shfl_xor_sync(0xffffffffu, s, o);
    float mean = s * (1.f/256.f);
    float s2 = 0.f;
#pragma unroll
    for (int i = 0; i < 8; i++) { float d = v[i] - mean; s2 += d*d; }
#pragma unroll
    for (int o = 16; o; o >>= 1) s2 += __shfl_xor_sync(0xffffffffu, s2, o);
    float rstd = rsqrtf(s2 * (1.f/256.f) + 1e-5f);
#pragma unroll
    for (int i = 0; i < 8; i++) {
        int cch = lane + i*32;
        float o = (v[i] - mean) * rstd * g[cch] + b[cch];
        if (out) {
            float ov = o;
            if (resid) ov += resid[(size_t)row * CC + cch];
            out[(size_t)row * CC + cch] = ov;
        }
        if (outh)
            outh[(size_t)row * CC + cch] = __float2half_rn(o);
    }
}

// ---------------------------------------------------------------------------
extern "C" void kernel_launch(void* const* d_in, const int* in_sizes, int n_in,
                              void* d_out, int out_size)
{
    const float* x     = (const float*)d_in[0];
    const float* src   = (const float*)d_in[1];
    const float* xpe   = (const float*)d_in[2];
    const float* spe   = (const float*)d_in[3];
    const float* xmask = (const float*)d_in[4];
    const float* smask = (const float*)d_in[5];
    const float* Wq    = (const float*)d_in[6];
    const float* Wk    = (const float*)d_in[7];
    const float* Wv    = (const float*)d_in[8];
    const float* Wm    = (const float*)d_in[9];
    const float* W1    = (const float*)d_in[10];
    const float* W2    = (const float*)d_in[11];
    const float* g1    = (const float*)d_in[12];
    const float* b1    = (const float*)d_in[13];
    const float* g2    = (const float*)d_in[14];
    const float* b2    = (const float*)d_in[15];
    float* out = (float*)d_out;

    float *query, *kvbuf, *Kpart, *KVpart, *Ksum, *KV, *msg, *h2;
    __half *xh, *sh, *qh, *m1h, *hbh, *wh;
    cudaGetSymbolAddress((void**)&query,  g_query);
    cudaGetSymbolAddress((void**)&kvbuf,  g_kv);
    cudaGetSymbolAddress((void**)&Kpart,  g_Kpart);
    cudaGetSymbolAddress((void**)&KVpart, g_KVpart);
    cudaGetSymbolAddress((void**)&Ksum,   g_Ksum);
    cudaGetSymbolAddress((void**)&KV,     g_KV);
    cudaGetSymbolAddress((void**)&msg,    g_msg);
    cudaGetSymbolAddress((void**)&h2,     g_h2);
    cudaGetSymbolAddress((void**)&xh,  g_xh);
    cudaGetSymbolAddress((void**)&sh,  g_sh);
    cudaGetSymbolAddress((void**)&qh,  g_qh);
    cudaGetSymbolAddress((void**)&m1h, g_m1h);
    cudaGetSymbolAddress((void**)&hbh, g_hbh);
    cudaGetSymbolAddress((void**)&wh,  g_wh);

    cudaFuncSetAttribute(hgemm<4,false>, cudaFuncAttributeMaxDynamicSharedMemorySize, SMEM_DYN);
    cudaFuncSetAttribute(hgemm<8,true>,  cudaFuncAttributeMaxDynamicSharedMemorySize, SMEM_DYN);
    cudaFuncSetAttribute(hgemm<8,false>, cudaFuncAttributeMaxDynamicSharedMemorySize, SMEM_DYN);

    dim3 gQ(CC / BN, MTOT / BM);            // (2, 256) N=256
    dim3 gKV(2*CC / BN, MSRC / BM);         // (4, 256) merged N=512
    dim3 gW1(2*CC / BN, MTOT / BM);         // (4, 256)

    // One-time converts
    convert_w<<<WH_TOT/4/256, 256>>>(Wq, Wk, Wv, Wm, W1, W2, wh);
    convert_act<<<MTOT*CC/4/256, 256>>>(x,   xh, MTOT*CC/4);
    convert_act<<<MSRC*CC/4/256, 256>>>(src, sh, MSRC*CC/4);

    // Q projection; merged K|V projection (weight arena rows 0..511 = Wk|Wv)
    hgemm<4,false><<<gQ, 256, SMEM_DYN>>>(xh, xh, 1<<30, CC, wh + WH_Q,
                                          query, nullptr, CC, 0);
    hgemm<4,false><<<gKV, 256, SMEM_DYN>>>(sh, sh, 1<<30, CC, wh + WH_K,
                                           kvbuf, nullptr, 2*CC, 0);

    // Linear-attention KV / Ksum (deterministic two-stage reduction)
    stageB_kernel<<<NB*SUBC, 256>>>(kvbuf, spe, smask, Kpart, KVpart);
    reduce_parts<<<(NB*CC + NB*KVSZ + 255) / 256, 256>>>(Kpart, KVpart, Ksum, KV);

    // Q-side: Z + queried (fp16 out)
    stageC_kernel<<<NB*SUBC, 256>>>(query, xpe, xmask, Ksum, KV, qh);

    // Message projection + LN1 (m1 as fp16)
    hgemm<4,false><<<gQ, 256, SMEM_DYN>>>(qh, qh, 1<<30, CC, wh + WH_M,
                                          msg, nullptr, CC, 0);
    ln_kernel<<<MTOT/8, 256>>>(msg, g1, b1, nullptr, nullptr, m1h);

    // MLP: h = relu([x, m1] @ W1^T) -> fp16; h2 = h @ W2^T -> fp32
    hgemm<8,true><<<gW1, 256, SMEM_DYN>>>(xh, m1h, CC, CC, wh + WH_1,
                                          nullptr, hbh, 2*CC, 1);
    hgemm<8,false><<<gQ, 256, SMEM_DYN>>>(hbh, hbh, 1<<30, 2*CC, wh + WH_2,
                                          h2, nullptr, CC, 0);

    // out = x + LN2(h2)
    ln_kernel<<<MTOT/8, 256>>>(h2, g2, b2, x, out, nullptr);
}

// round 14
// speedup vs baseline: 1.0589x; 1.0589x over previous
#include <cuda_runtime.h>
#include <cuda_fp16.h>
#include <math.h>
#include <stdint.h>

// Problem constants
#define NB 4
#define LQ 8192
#define SSEQ 8192
#define CC 256
#define HH 8
#define DD 32
#define MTOT (NB*LQ)     // 32768 query rows
#define MSRC (NB*SSEQ)   // 32768 source rows
#define SUBC 256         // 32-row chunks per batch
#define KVSZ (HH*DD*DD)  // 8192 per batch

// fp16 weight arena segment offsets (halves)
#define WH_Q  0
#define WH_K  65536      // Wk rows 0..255 then Wv rows 256..511 (contiguous => merged)
#define WH_M  196608
#define WH_1  262144
#define WH_2  524288
#define WH_TOT 655360

// Scratch (device globals: no allocation allowed)
__device__ float g_Kpart[(size_t)NB*SUBC*CC];
__device__ float g_KVpart[(size_t)NB*SUBC*KVSZ];
__device__ float g_Ksum[NB*CC];
__device__ float g_KV[NB*KVSZ];
__device__ float g_msg[MTOT*CC];
__device__ float g_h2[MTOT*CC];
// fp16 activation tensors
__device__ __half g_xh[MTOT*CC];
__device__ __half g_sh[MSRC*CC];
__device__ __half g_qryh[MTOT*CC];              // query (fp16, GEMM out)
__device__ __half g_kvh[(size_t)MSRC*2*CC];     // merged key|value fp16, stride 512
__device__ __half g_qh[MTOT*CC];                // queried
__device__ __half g_m1h[MTOT*CC];
__device__ __half g_hbh[(size_t)MTOT*2*CC];
__device__ __half g_wh[WH_TOT];

// ===========================================================================
// Helpers
// ===========================================================================
__device__ __forceinline__ uint32_t smem_u32(const void* p) {
    uint32_t a;
    asm("{ .reg .u64 t; cvta.to.shared.u64 t, %1; cvt.u32.u64 %0, t; }"
        : "=r"(a) : "l"(p));
    return a;
}

#define CP_ASYNC16(dst_u32, src_ptr) \
    asm volatile("cp.async.cg.shared.global [%0], [%1], 16;" \
        :: "r"(dst_u32), "l"(src_ptr))
#define CP_COMMIT() asm volatile("cp.async.commit_group;")
#define CP_WAIT3()  asm volatile("cp.async.wait_group 3;")

#define LDSM_X4(r0,r1,r2,r3, addr) \
    asm volatile("ldmatrix.sync.aligned.m8n8.x4.shared.b16 {%0,%1,%2,%3}, [%4];" \
        : "=r"(r0), "=r"(r1), "=r"(r2), "=r"(r3) : "r"(addr))

__device__ __forceinline__ void mma16816(float* c, const uint32_t* a, const uint32_t* b) {
    asm volatile(
        "mma.sync.aligned.m16n8k16.row.col.f32.f16.f16.f32 "
        "{%0,%1,%2,%3}, {%4,%5,%6,%7}, {%8,%9}, {%0,%1,%2,%3};"
        : "+f"(c[0]), "+f"(c[1]), "+f"(c[2]), "+f"(c[3])
        : "r"(a[0]), "r"(a[1]), "r"(a[2]), "r"(a[3]), "r"(b[0]), "r"(b[1]));
}

// ===========================================================================
// One-time converts (round-to-nearest fp16)
// ===========================================================================
__global__ void convert_act(const float* __restrict__ in,
                            __half* __restrict__ hi, int n4)
{
    int i = blockIdx.x * 256 + threadIdx.x;
    if (i >= n4) return;
    float4 v = ((const float4*)in)[i];
    __half h[4] = {__float2half_rn(v.x), __float2half_rn(v.y),
                   __float2half_rn(v.z), __float2half_rn(v.w)};
    ((uint2*)hi)[i] = *(uint2*)h;
}

__global__ void convert_w(const float* __restrict__ Wq, const float* __restrict__ Wk,
                          const float* __restrict__ Wv, const float* __restrict__ Wm,
                          const float* __restrict__ W1, const float* __restrict__ W2,
                          __half* __restrict__ arena)
{
    int idx = (blockIdx.x * 256 + threadIdx.x) * 4;
    if (idx >= WH_TOT) return;
    const float* src; int off;
    if (idx < WH_1) {
        int seg = idx >> 16;
        src = (seg == 0) ? Wq : (seg == 1) ? Wk : (seg == 2) ? Wv : Wm;
        off = idx & 65535;
    } else if (idx < WH_2) { src = W1; off = idx - WH_1; }
    else                   { src = W2; off = idx - WH_2; }
    float4 v = *(const float4*)(src + off);
    __half h[4] = {__float2half_rn(v.x), __float2half_rn(v.y),
                   __float2half_rn(v.z), __float2half_rn(v.w)};
    *(uint2*)(arena + idx) = *(uint2*)h;
}

// ===========================================================================
// Tensor-core GEMM, cp.async 5-stage pipeline, single-term fp16:
//   Y[m,n] = act( sum_k Ah[m,k] * Bh[n,k] )
// Tile 128x128xBK32, 256 threads / 8 warps, warp tile 64x32, 2 CTAs/SM.
// Template NK = K/32 (fully unrolls, NK >= 5), SPLIT = concat-A (W1 GEMM).
// ===========================================================================
#define BM 128
#define BN 128
#define BK 32
#define STAGES 5
#define SSTR 40                 // padded fp16 row stride (80B): conflict-free ldmatrix
#define SA (128*SSTR*2)         // 10240 B (A tile)
#define SB (128*SSTR*2)         // 10240 B (B tile)
#define STG (SA + SB)           // 20480
#define SMEM_DYN (STAGES*STG)   // 102400 (2 CTAs/SM: 204.8KB <= 227KB)

template<int NK, bool SPLIT>
__global__ void __launch_bounds__(256, 2) hgemm(
    const __half* __restrict__ Ah, const __half* __restrict__ A2h,
    int Ksplit, int lda, const __half* __restrict__ W,
    float* __restrict__ Y, __half* __restrict__ Yh,
    int Nn, int relu)
{
    constexpr int K = NK * BK;
    extern __shared__ __align__(16) char smem[];
    const uint32_t sb = smem_u32(smem);

    const int tid = threadIdx.x;
    const int lane = tid & 31;
    const int wid = tid >> 5;
    const int bm = blockIdx.y * BM;
    const int bn = blockIdx.x * BN;
    const int wm = (wid >> 2) * 64;   // 0/64
    const int wn = (wid & 3) * 32;    // 0..96

    // loader mapping: each thread cp.asyncs 16B at rows arow and arow+64
    const int arow = tid >> 2;          // 0..63
    const int acol = (tid & 3) * 8;     // 0,8,16,24
    const uint32_t sOff0 = (uint32_t)(arow * SSTR + acol) * 2;
    const uint32_t sOff1 = sOff0 + (uint32_t)(64 * SSTR * 2);

    // issue loads for chunk ck into stage st
    auto load_chunk = [&](int ck, int st) {
        const int k0 = ck * BK;
        const __half* ah = Ah;
        int kk0 = k0;
        if (SPLIT && k0 >= Ksplit) { ah = A2h; kk0 = k0 - Ksplit; }
        const uint32_t base = sb + st * STG;
        CP_ASYNC16(base + sOff0, ah + (size_t)(bm + arow) * lda + kk0 + acol);
        CP_ASYNC16(base + sOff1, ah + (size_t)(bm + 64 + arow) * lda + kk0 + acol);
        CP_ASYNC16(base + SA + sOff0, W + (size_t)(bn + arow) * K + k0 + acol);
        CP_ASYNC16(base + SA + sOff1, W + (size_t)(bn + 64 + arow) * K + k0 + acol);
    };

    float c[4][4][4];
#pragma unroll
    for (int mi = 0; mi < 4; mi++)
#pragma unroll
        for (int ni = 0; ni < 4; ni++)
#pragma unroll
            for (int i = 0; i < 4; i++) c[mi][ni][i] = 0.f;

    // prefetch STAGES-1 = 4 chunks
#pragma unroll
    for (int p = 0; p < STAGES - 1; p++) {
        load_chunk(p, p); CP_COMMIT();
    }

#pragma unroll
    for (int ck = 0; ck < NK; ck++) {
        CP_WAIT3();        // oldest (chunk ck) complete; <=3 groups in flight
        __syncthreads();   // orders mma(ck-1) of all warps before that slot is refilled

        const int nc = ck + STAGES - 1;
        if (nc < NK) load_chunk(nc, nc % STAGES);
        CP_COMMIT();

        const uint32_t sAh = sb + (ck % STAGES) * STG;
        const uint32_t sBh = sAh + SA;
#pragma unroll
        for (int kk = 0; kk < 2; kk++) {
            uint32_t ahf[4][4], bhf[4][2];
            // A frags: 4 x ldmatrix.x4 (rows wm+mi*16+(lane&15), k kk*16+(lane>>4)*8)
            const uint32_t aoff =
                ((wm + (lane & 15)) * SSTR + kk * 16 + (lane >> 4) * 8) * 2;
#pragma unroll
            for (int mi = 0; mi < 4; mi++)
                LDSM_X4(ahf[mi][0], ahf[mi][1], ahf[mi][2], ahf[mi][3],
                        sAh + aoff + mi * 16 * SSTR * 2);
            // B frags: 2 x ldmatrix.x4, each covers ni pair (2p, 2p+1)
            const uint32_t boff =
                ((wn + (lane >> 4) * 8 + (lane & 7)) * SSTR
                 + kk * 16 + ((lane >> 3) & 1) * 8) * 2;
#pragma unroll
            for (int p = 0; p < 2; p++)
                LDSM_X4(bhf[2*p][0], bhf[2*p][1], bhf[2*p+1][0], bhf[2*p+1][1],
                        sBh + boff + p * 16 * SSTR * 2);
#pragma unroll
            for (int mi = 0; mi < 4; mi++)
#pragma unroll
                for (int ni = 0; ni < 4; ni++)
                    mma16816(c[mi][ni], ahf[mi], bhf[ni]);
        }
    }

    // Epilogue: c frag mapping (m16n8): rows lane/4 (+8), cols (lane%4)*2 (+1)
    const int grp = lane >> 2;
    const int tg = (lane & 3) * 2;
#pragma unroll
    for (int mi = 0; mi < 4; mi++)
#pragma unroll
        for (int ni = 0; ni < 4; ni++) {
            float v[4] = {c[mi][ni][0], c[mi][ni][1], c[mi][ni][2], c[mi][ni][3]};
            if (relu) {
#pragma unroll
                for (int i = 0; i < 4; i++) v[i] = fmaxf(v[i], 0.f);
            }
            const size_t r0 = (size_t)(bm + wm + mi * 16 + grp) * Nn + bn + wn + ni * 8 + tg;
            const size_t r1 = r0 + (size_t)8 * Nn;
            if (Y) {
                *(float2*)(Y + r0) = make_float2(v[0], v[1]);
                *(float2*)(Y + r1) = make_float2(v[2], v[3]);
            }
            if (Yh) {
                __half h[4] = {__float2half_rn(v[0]), __float2half_rn(v[1]),
                               __float2half_rn(v[2]), __float2half_rn(v[3])};
                *(uint32_t*)(Yh + r0) = *(uint32_t*)&h[0];
                *(uint32_t*)(Yh + r1) = *(uint32_t*)&h[2];
            }
        }
}

// ---------------------------------------------------------------------------
// Stage B (warp-per-head, 32-row chunks, grid 1024); reads merged fp16 kv
// buffer (row stride 512: key at col c, value at col 256+c).
// ---------------------------------------------------------------------------
__global__ void __launch_bounds__(256) stageB_kernel(
    const __half* __restrict__ kvbuf,
    const float* __restrict__ spe, const float* __restrict__ smask,
    float* __restrict__ Kpart, float* __restrict__ KVpart)
{
    const int n = blockIdx.x / SUBC;
    const int chunk = blockIdx.x % SUBC;
    const int s0 = chunk * 32;
    const int h = threadIdx.x >> 5;
    const int lane = threadIdx.x & 31;
    const int c = h * 32 + lane;

    float acc[32];
#pragma unroll
    for (int d = 0; d < 32; d++) acc[d] = 0.f;
    float accKs = 0.f;

    const size_t pebase = ((size_t)n * SSEQ + s0) * CC;
    const size_t kvbase = ((size_t)n * SSEQ + s0) * (2*CC);
    const float* mrow = smask + (size_t)n * SSEQ + s0;
    for (int r = 0; r < 32; r++) {
        const size_t kvrow = kvbase + (size_t)r * (2*CC);
        float kc = __half2float(kvbuf[kvrow + c]);
        float vc = __half2float(kvbuf[kvrow + CC + c]);
        float2 pe = *(const float2*)(spe + (pebase + (size_t)r * CC + c) * 2);
        float m  = mrow[r];
        float kp = __shfl_xor_sync(0xffffffffu, kc, 1);
        float vp = __shfl_xor_sync(0xffffffffu, vc, 1);
        float k2 = (lane & 1) ? kp : -kp;
        float v2 = (lane & 1) ? vp : -vp;
        float Kf   = (kc > 0.f ? kc + 1.f : expf(kc)) * m;
        float Kpos = (kc * pe.x + k2 * pe.y) * m;
        float Vr   = (vc * pe.x + v2 * pe.y) * m;
        accKs += Kf;
#pragma unroll
        for (int d = 0; d < 32; d++) {
            float a = __shfl_sync(0xffffffffu, Kpos, d);
            acc[d] = fmaf(a, Vr, acc[d]);
        }
    }
    Kpart[(size_t)(n*SUBC + chunk)*CC + c] = accKs;
    const size_t kvb = (size_t)(n*SUBC + chunk)*KVSZ + h*1024;
#pragma unroll
    for (int d = 0; d < 32; d++)
        KVpart[kvb + d*32 + lane] = acc[d];
}

// Fixed-order reduction of chunk partials -> Ksum, KV (deterministic)
__global__ void __launch_bounds__(256) reduce_parts(
    const float* __restrict__ Kpart, const float* __restrict__ KVpart,
    float* __restrict__ Ksum, float* __restrict__ KV)
{
    int idx = blockIdx.x * 256 + threadIdx.x;
    if (idx < NB*CC) {
        int n = idx / CC, c = idx % CC;
        float s = 0.f;
        for (int ch = 0; ch < SUBC; ch++)
            s += Kpart[(size_t)(n*SUBC + ch)*CC + c];
        Ksum[idx] = s;
        return;
    }
    int kidx = idx - NB*CC;
    if (kidx < NB*KVSZ) {
        int n = kidx / KVSZ, e = kidx % KVSZ;
        float s = 0.f;
        for (int ch = 0; ch < SUBC; ch++)
            s += KVpart[(size_t)(n*SUBC + ch)*KVSZ + e];
        KV[kidx] = s;
    }
}

// ---------------------------------------------------------------------------
// Stage C (warp-per-head): reads fp16 query, writes queried as fp16
// ---------------------------------------------------------------------------
__global__ void __launch_bounds__(256) stageC_kernel(
    const __half* __restrict__ query, const float* __restrict__ xpe,
    const float* __restrict__ xmask, const float* __restrict__ Ksum,
    const float* __restrict__ KV, __half* __restrict__ qh)
{
    const int n = blockIdx.x / SUBC;
    const int l0 = (blockIdx.x % SUBC) * 32;
    const int h = threadIdx.x >> 5;
    const int lane = threadIdx.x & 31;
    const int c = h * 32 + lane;

    float kvreg[32];
#pragma unroll
    for (int d = 0; d < 32; d++)
        kvreg[d] = KV[(size_t)n*KVSZ + h*1024 + d*32 + lane];
    const float ks = Ksum[n*CC + c];

    const size_t base = ((size_t)n * LQ + l0) * CC;
    const float* mrow = xmask + (size_t)n * LQ + l0;
    for (int r = 0; r < 32; r++) {
        const size_t row = base + (size_t)r * CC;
        float q  = __half2float(query[row + c]);
        float2 pe = *(const float2*)(xpe + (row + c) * 2);
        float m  = mrow[r];
        float qp = __shfl_xor_sync(0xffffffffu, q, 1);
        float q2 = (lane & 1) ? qp : -qp;
        float Qf   = (q > 0.f ? q + 1.f : expf(q)) * m;
        float Qpos = (q * pe.x + q2 * pe.y) * m;

        float p = Qf * ks;
#pragma unroll
        for (int o = 16; o; o >>= 1) p += __shfl_xor_sync(0xffffffffu, p, o);
        float z = 1.f / (p + 1e-6f);

        float out = 0.f;
#pragma unroll
        for (int d = 0; d < 32; d++) {
            float a = __shfl_sync(0xffffffffu, Qpos, d);
            out = fmaf(a, kvreg[d], out);
        }
        qh[row + c] = __float2half_rn(out * z);
    }
}

// ---------------------------------------------------------------------------
// LayerNorm over last dim (256); one warp per row.
// Writes fp32 (with optional residual) and/or fp16.
// ---------------------------------------------------------------------------
__global__ void __launch_bounds__(256) ln_kernel(
    const float* __restrict__ in, const float* __restrict__ g,
    const float* __restrict__ b, const float* __restrict__ resid,
    float* __restrict__ out, __half* __restrict__ outh)
{
    const int row = blockIdx.x * 8 + (threadIdx.x >> 5);
    const int lane = threadIdx.x & 31;
    const float* p = in + (size_t)row * CC;
    float v[8];
    float s = 0.f;
#pragma unroll
    for (int i = 0; i < 8; i++) { v[i] = p[lane + i*32]; s += v[i]; }
#pragma unroll
    for (int o = 16; o; o >>= 1) s += __shfl_xor_sync(0xffffffffu, s, o);
    float mean = s * (1.f/256.f);
    float s2 = 0.f;
#pragma unroll
    for (int i = 0; i < 8; i++) { float d = v[i] - mean; s2 += d*d; }
#pragma unroll
    for (int o = 16; o; o >>= 1) s2 += __shfl_xor_sync(0xffffffffu, s2, o);
    float rstd = rsqrtf(s2 * (1.f/256.f) + 1e-5f);
#pragma unroll
    for (int i = 0; i < 8; i++) {
        int cch = lane + i*32;
        float o = (v[i] - mean) * rstd * g[cch] + b[cch];
        if (out) {
            float ov = o;
            if (resid) ov += resid[(size_t)row * CC + cch];
            out[(size_t)row * CC + cch] = ov;
        }
        if (outh)
            outh[(size_t)row * CC + cch] = __float2half_rn(o);
    }
}

// ---------------------------------------------------------------------------
extern "C" void kernel_launch(void* const* d_in, const int* in_sizes, int n_in,
                              void* d_out, int out_size)
{
    const float* x     = (const float*)d_in[0];
    const float* src   = (const float*)d_in[1];
    const float* xpe   = (const float*)d_in[2];
    const float* spe   = (const float*)d_in[3];
    const float* xmask = (const float*)d_in[4];
    const float* smask = (const float*)d_in[5];
    const float* Wq    = (const float*)d_in[6];
    const float* Wk    = (const float*)d_in[7];
    const float* Wv    = (const float*)d_in[8];
    const float* Wm    = (const float*)d_in[9];
    const float* W1    = (const float*)d_in[10];
    const float* W2    = (const float*)d_in[11];
    const float* g1    = (const float*)d_in[12];
    const float* b1    = (const float*)d_in[13];
    const float* g2    = (const float*)d_in[14];
    const float* b2    = (const float*)d_in[15];
    float* out = (float*)d_out;

    float *Kpart, *KVpart, *Ksum, *KV, *msg, *h2;
    __half *xh, *sh, *qryh, *kvh, *qh, *m1h, *hbh, *wh;
    cudaGetSymbolAddress((void**)&Kpart,  g_Kpart);
    cudaGetSymbolAddress((void**)&KVpart, g_KVpart);
    cudaGetSymbolAddress((void**)&Ksum,   g_Ksum);
    cudaGetSymbolAddress((void**)&KV,     g_KV);
    cudaGetSymbolAddress((void**)&msg,    g_msg);
    cudaGetSymbolAddress((void**)&h2,     g_h2);
    cudaGetSymbolAddress((void**)&xh,   g_xh);
    cudaGetSymbolAddress((void**)&sh,   g_sh);
    cudaGetSymbolAddress((void**)&qryh, g_qryh);
    cudaGetSymbolAddress((void**)&kvh,  g_kvh);
    cudaGetSymbolAddress((void**)&qh,   g_qh);
    cudaGetSymbolAddress((void**)&m1h,  g_m1h);
    cudaGetSymbolAddress((void**)&hbh,  g_hbh);
    cudaGetSymbolAddress((void**)&wh,   g_wh);

    cudaFuncSetAttribute(hgemm<8,false>,  cudaFuncAttributeMaxDynamicSharedMemorySize, SMEM_DYN);
    cudaFuncSetAttribute(hgemm<16,true>,  cudaFuncAttributeMaxDynamicSharedMemorySize, SMEM_DYN);
    cudaFuncSetAttribute(hgemm<16,false>, cudaFuncAttributeMaxDynamicSharedMemorySize, SMEM_DYN);

    dim3 gQ(CC / BN, MTOT / BM);            // (2, 256) N=256
    dim3 gKV(2*CC / BN, MSRC / BM);         // (4, 256) merged N=512
    dim3 gW1(2*CC / BN, MTOT / BM);         // (4, 256)

    // One-time converts
    convert_w<<<WH_TOT/4/256, 256>>>(Wq, Wk, Wv, Wm, W1, W2, wh);
    convert_act<<<MTOT*CC/4/256, 256>>>(x,   xh, MTOT*CC/4);
    convert_act<<<MSRC*CC/4/256, 256>>>(src, sh, MSRC*CC/4);

    // Q projection (fp16 out); merged K|V projection (fp16 out)
    hgemm<8,false><<<gQ, 256, SMEM_DYN>>>(xh, xh, 1<<30, CC, wh + WH_Q,
                                          nullptr, qryh, CC, 0);
    hgemm<8,false><<<gKV, 256, SMEM_DYN>>>(sh, sh, 1<<30, CC, wh + WH_K,
                                           nullptr, kvh, 2*CC, 0);

    // Linear-attention KV / Ksum (deterministic two-stage reduction)
    stageB_kernel<<<NB*SUBC, 256>>>(kvh, spe, smask, Kpart, KVpart);
    reduce_parts<<<(NB*CC + NB*KVSZ + 255) / 256, 256>>>(Kpart, KVpart, Ksum, KV);

    // Q-side: Z + queried (fp16 out)
    stageC_kernel<<<NB*SUBC, 256>>>(qryh, xpe, xmask, Ksum, KV, qh);

    // Message projection + LN1 (m1 as fp16)
    hgemm<8,false><<<gQ, 256, SMEM_DYN>>>(qh, qh, 1<<30, CC, wh + WH_M,
                                          msg, nullptr, CC, 0);
    ln_kernel<<<MTOT/8, 256>>>(msg, g1, b1, nullptr, nullptr, m1h);

    // MLP: h = relu([x, m1] @ W1^T) -> fp16; h2 = h @ W2^T -> fp32
    hgemm<16,true><<<gW1, 256, SMEM_DYN>>>(xh, m1h, CC, CC, wh + WH_1,
                                           nullptr, hbh, 2*CC, 1);
    hgemm<16,false><<<gQ, 256, SMEM_DYN>>>(hbh, hbh, 1<<30, 2*CC, wh + WH_2,
                                           h2, nullptr, CC, 0);

    // out = x + LN2(h2)
    ln_kernel<<<MTOT/8, 256>>>(h2, g2, b2, x, out, nullptr);
}